// round 6
// baseline (speedup 1.0000x reference)
#include <cuda_runtime.h>

// Seq2Seq GRU encoder/decoder, persistent per-CTA batch-slice kernel.
// R3: packed fma.rn.f32x2 along the gate-column dimension; h/x stored
// duplicated in smem so pair operands need no per-iteration packing.
// (R2 retry: fixed Smem alignment — all vector-accessed arrays __align__(16).)
#define SEQ_LEN   256
#define LABEL_LEN 128
#define BATCH     8192
#define NF        8
#define NO        8
#define HID       64
#define G3        192   // 3*HID

#define ROWS      64                 // batch rows per CTA
#define NCTA      (BATCH / ROWS)     // 128
#define NTHREADS  256                // 16 (col groups) x 16 (row groups)

typedef unsigned long long u64;

struct Smem {
    __align__(16) float whh_t[HID * G3];       // [k][c] : Whh transposed
    __align__(16) float wih_t[NF * G3];        // [f][c]
    __align__(16) float wout_t[HID * NO];      // [k][o]
    __align__(16) float brz[2 * HID];          // bih + bhh for r,z gates
    __align__(16) float bin_[HID];             // bih n-gate
    __align__(16) float bhn[HID];              // bhh n-gate
    __align__(16) float bout_s[NO];
    __align__(16) float h_dup[HID * 2 * ROWS]; // [k][2*row] : h duplicated (h,h)
    __align__(16) float x_dup[NF * 2 * ROWS];  // [f][2*row] : input duplicated
};

__device__ __forceinline__ float sigf(float x) {
    return __fdividef(1.0f, 1.0f + __expf(-x));
}
__device__ __forceinline__ float tanh_(float x) {
    return __fdividef(2.0f, 1.0f + __expf(-2.0f * x)) - 1.0f;
}

__device__ __forceinline__ u64 fma2(u64 a, u64 b, u64 c) {
    u64 d;
    asm("fma.rn.f32x2 %0, %1, %2, %3;" : "=l"(d) : "l"(a), "l"(b), "l"(c));
    return d;
}
__device__ __forceinline__ float2 unpack2(u64 v) {
    float2 r;
    asm("mov.b64 {%0, %1}, %2;" : "=f"(r.x), "=f"(r.y) : "l"(v));
    return r;
}

__device__ void load_phase_weights(Smem* s, const float* Wih, const float* Whh,
                                   const float* bih, const float* bhh) {
    int tid = threadIdx.x;
    for (int idx = tid; idx < G3 * HID; idx += NTHREADS) {
        int c = idx / HID, k = idx % HID;
        s->whh_t[k * G3 + c] = Whh[idx];
    }
    for (int idx = tid; idx < G3 * NF; idx += NTHREADS) {
        int c = idx / NF, f = idx % NF;
        s->wih_t[f * G3 + c] = Wih[idx];
    }
    for (int c = tid; c < 2 * HID; c += NTHREADS) s->brz[c] = bih[c] + bhh[c];
    for (int c = tid; c < HID; c += NTHREADS) {
        s->bin_[c] = bih[2 * HID + c];
        s->bhn[c]  = bhh[2 * HID + c];
    }
}

// One GRU step. Preconditions: x_dup, h_dup populated and synced.
// Postcondition: h_dup updated, synced.
__device__ __forceinline__ void gru_step(Smem* s, int tx, int ty) {
    const int c0 = tx * 4;   // hidden-column group (0..60)
    const int r0 = ty * 4;   // batch-row group (0..60)

    // Accumulators: f32x2 pairs over j (columns c0+0/1 and c0+2/3), 4 rows.
    u64 ar[4][2], az[4][2], ai[4][2], ah[4][2];
    {
        const ulonglong2 br = *(const ulonglong2*)&s->brz[c0];
        const ulonglong2 bz = *(const ulonglong2*)&s->brz[HID + c0];
        const ulonglong2 bi = *(const ulonglong2*)&s->bin_[c0];
        const ulonglong2 bh = *(const ulonglong2*)&s->bhn[c0];
        #pragma unroll
        for (int i = 0; i < 4; i++) {
            ar[i][0] = br.x; ar[i][1] = br.y;
            az[i][0] = bz.x; az[i][1] = bz.y;
            ai[i][0] = bi.x; ai[i][1] = bi.y;
            ah[i][0] = bh.x; ah[i][1] = bh.y;
        }
    }

    // Input contribution (k over NF=8): r, z, and in-part of n
    #pragma unroll
    for (int k = 0; k < NF; k++) {
        const float* xd = &s->x_dup[k * 2 * ROWS + 2 * r0];
        const ulonglong2 xpA = *(const ulonglong2*)xd;        // (x0,x0),(x1,x1)
        const ulonglong2 xpB = *(const ulonglong2*)(xd + 4);  // (x2,x2),(x3,x3)
        const u64 xp[4] = {xpA.x, xpA.y, xpB.x, xpB.y};
        const ulonglong2 wr = *(const ulonglong2*)&s->wih_t[k * G3 + c0];
        const ulonglong2 wz = *(const ulonglong2*)&s->wih_t[k * G3 + HID + c0];
        const ulonglong2 wn = *(const ulonglong2*)&s->wih_t[k * G3 + 2 * HID + c0];
        #pragma unroll
        for (int i = 0; i < 4; i++) {
            ar[i][0] = fma2(xp[i], wr.x, ar[i][0]);
            ar[i][1] = fma2(xp[i], wr.y, ar[i][1]);
            az[i][0] = fma2(xp[i], wz.x, az[i][0]);
            az[i][1] = fma2(xp[i], wz.y, az[i][1]);
            ai[i][0] = fma2(xp[i], wn.x, ai[i][0]);
            ai[i][1] = fma2(xp[i], wn.y, ai[i][1]);
        }
    }

    // Hidden contribution (k over HID=64): r, z, and h-part of n
    #pragma unroll 4
    for (int k = 0; k < HID; k++) {
        const float* hd = &s->h_dup[k * 2 * ROWS + 2 * r0];
        const ulonglong2 hpA = *(const ulonglong2*)hd;
        const ulonglong2 hpB = *(const ulonglong2*)(hd + 4);
        const u64 hp[4] = {hpA.x, hpA.y, hpB.x, hpB.y};
        const ulonglong2 wr = *(const ulonglong2*)&s->whh_t[k * G3 + c0];
        const ulonglong2 wz = *(const ulonglong2*)&s->whh_t[k * G3 + HID + c0];
        const ulonglong2 wn = *(const ulonglong2*)&s->whh_t[k * G3 + 2 * HID + c0];
        #pragma unroll
        for (int i = 0; i < 4; i++) {
            ar[i][0] = fma2(hp[i], wr.x, ar[i][0]);
            ar[i][1] = fma2(hp[i], wr.y, ar[i][1]);
            az[i][0] = fma2(hp[i], wz.x, az[i][0]);
            az[i][1] = fma2(hp[i], wz.y, az[i][1]);
            ah[i][0] = fma2(hp[i], wn.x, ah[i][0]);
            ah[i][1] = fma2(hp[i], wn.y, ah[i][1]);
        }
    }

    // Unpack accumulators to scalars
    float Ar[4][4], Az[4][4], Ai[4][4], Ah[4][4];
    #pragma unroll
    for (int i = 0; i < 4; i++)
        #pragma unroll
        for (int jp = 0; jp < 2; jp++) {
            float2 t;
            t = unpack2(ar[i][jp]); Ar[i][2*jp] = t.x; Ar[i][2*jp+1] = t.y;
            t = unpack2(az[i][jp]); Az[i][2*jp] = t.x; Az[i][2*jp+1] = t.y;
            t = unpack2(ai[i][jp]); Ai[i][2*jp] = t.x; Ai[i][2*jp+1] = t.y;
            t = unpack2(ah[i][jp]); Ah[i][2*jp] = t.x; Ah[i][2*jp+1] = t.y;
        }

    // Gates + state update. hnew[j][i] layout for the transposed dup store.
    float hnew[4][4];
    #pragma unroll
    for (int j = 0; j < 4; j++) {
        const float* hd = &s->h_dup[(c0 + j) * 2 * ROWS + 2 * r0];
        const float4 h01 = *(const float4*)hd;        // (h0,h0,h1,h1)
        const float4 h23 = *(const float4*)(hd + 4);  // (h2,h2,h3,h3)
        const float hoa[4] = {h01.x, h01.z, h23.x, h23.z};
        #pragma unroll
        for (int i = 0; i < 4; i++) {
            float r = sigf(Ar[i][j]);
            float z = sigf(Az[i][j]);
            float n = tanh_(fmaf(r, Ah[i][j], Ai[i][j]));
            hnew[j][i] = fmaf(z, hoa[i] - n, n);   // (1-z)*n + z*h
        }
    }
    __syncthreads();   // all reads of old h_dup complete
    #pragma unroll
    for (int j = 0; j < 4; j++) {
        float* hd = &s->h_dup[(c0 + j) * 2 * ROWS + 2 * r0];
        *(float4*)hd       = make_float4(hnew[j][0], hnew[j][0], hnew[j][1], hnew[j][1]);
        *(float4*)(hd + 4) = make_float4(hnew[j][2], hnew[j][2], hnew[j][3], hnew[j][3]);
    }
    __syncthreads();   // new h_dup visible
}

extern __shared__ __align__(16) float smem_raw[];

__global__ void __launch_bounds__(NTHREADS)
seq2seq_gru_kernel(const float* __restrict__ x,  const float* __restrict__ xy,
                   const float* __restrict__ eWih, const float* __restrict__ eWhh,
                   const float* __restrict__ ebih, const float* __restrict__ ebhh,
                   const float* __restrict__ dWih, const float* __restrict__ dWhh,
                   const float* __restrict__ dbih, const float* __restrict__ dbhh,
                   const float* __restrict__ Wout, const float* __restrict__ bout,
                   float* __restrict__ out)
{
    Smem* s = (Smem*)smem_raw;
    const int tid = threadIdx.x;
    const int tx = tid % 16;
    const int ty = tid / 16;
    const int b0 = blockIdx.x * ROWS;

    // init h = 0
    for (int i = tid; i < HID * 2 * ROWS; i += NTHREADS) s->h_dup[i] = 0.0f;

    load_phase_weights(s, eWih, eWhh, ebih, ebhh);

    for (int idx = tid; idx < HID * NO; idx += NTHREADS) {
        int o = idx / HID, k = idx % HID;
        s->wout_t[k * NO + o] = Wout[idx];
    }
    if (tid < NO) s->bout_s[tid] = bout[tid];
    __syncthreads();

    // ----- Encoder: 256 steps -----
    for (int t = 0; t < SEQ_LEN; t++) {
        if (tid < ROWS) {
            const float* xr = x + ((size_t)t * BATCH + b0 + tid) * NF;
            float4 a = *(const float4*)xr;
            float4 b = *(const float4*)(xr + 4);
            const float v[8] = {a.x, a.y, a.z, a.w, b.x, b.y, b.z, b.w};
            #pragma unroll
            for (int f = 0; f < NF; f++)
                *(float2*)&s->x_dup[f * 2 * ROWS + 2 * tid] = make_float2(v[f], v[f]);
        }
        __syncthreads();
        gru_step(s, tx, ty);
    }

    // ----- Switch to decoder weights; seed input with xy[0] -----
    load_phase_weights(s, dWih, dWhh, dbih, dbhh);
    if (tid < ROWS) {
        const float* xr = xy + ((size_t)b0 + tid) * NO;   // xy[0]
        float4 a = *(const float4*)xr;
        float4 b = *(const float4*)(xr + 4);
        const float v[8] = {a.x, a.y, a.z, a.w, b.x, b.y, b.z, b.w};
        #pragma unroll
        for (int f = 0; f < NO; f++)
            *(float2*)&s->x_dup[f * 2 * ROWS + 2 * tid] = make_float2(v[f], v[f]);
    }
    __syncthreads();

    // ----- Decoder: 128 steps, autoregressive through output projection -----
    for (int t = 0; t < LABEL_LEN; t++) {
        gru_step(s, tx, ty);   // consumes x_dup, updates h_dup (ends synced)

        // Output projection: 64 rows x 8 outs = 512 dots; 2 per thread.
        const int o    = tid & 7;
        const int row0 = tid >> 3;        // 0..31
        const int row1 = row0 + 32;
        float acc0 = 0.0f, acc1 = 0.0f;
        #pragma unroll 8
        for (int k = 0; k < HID; k++) {
            const float w = s->wout_t[k * NO + o];
            acc0 = fmaf(s->h_dup[k * 2 * ROWS + 2 * row0], w, acc0);
            acc1 = fmaf(s->h_dup[k * 2 * ROWS + 2 * row1], w, acc1);
        }
        acc0 += s->bout_s[o];
        acc1 += s->bout_s[o];

        float* op = out + ((size_t)t * BATCH + b0) * NO;
        op[row0 * NO + o] = acc0;
        op[row1 * NO + o] = acc1;

        // Feed back as next decoder input (duplicated pairs)
        *(float2*)&s->x_dup[o * 2 * ROWS + 2 * row0] = make_float2(acc0, acc0);
        *(float2*)&s->x_dup[o * 2 * ROWS + 2 * row1] = make_float2(acc1, acc1);
        __syncthreads();
    }
}

extern "C" void kernel_launch(void* const* d_in, const int* in_sizes, int n_in,
                              void* d_out, int out_size) {
    const float* x    = (const float*)d_in[0];
    const float* xy   = (const float*)d_in[1];
    const float* eWih = (const float*)d_in[2];
    const float* eWhh = (const float*)d_in[3];
    const float* ebih = (const float*)d_in[4];
    const float* ebhh = (const float*)d_in[5];
    const float* dWih = (const float*)d_in[6];
    const float* dWhh = (const float*)d_in[7];
    const float* dbih = (const float*)d_in[8];
    const float* dbhh = (const float*)d_in[9];
    const float* Wout = (const float*)d_in[10];
    const float* bout = (const float*)d_in[11];
    float* out = (float*)d_out;

    const int smem_bytes = (int)sizeof(Smem);
    cudaFuncSetAttribute(seq2seq_gru_kernel,
                         cudaFuncAttributeMaxDynamicSharedMemorySize, smem_bytes);

    seq2seq_gru_kernel<<<NCTA, NTHREADS, smem_bytes>>>(
        x, xy, eWih, eWhh, ebih, ebhh, dWih, dWhh, dbih, dbhh, Wout, bout, out);
}

// round 9
// speedup vs baseline: 2.5565x; 2.5565x over previous
#include <cuda_runtime.h>
#include <cuda_bf16.h>
#include <cstdint>

// Seq2Seq GRU via mma.sync bf16 (HMMA), 2-way bf16 split (~fp32 precision).
// A[64 x 88] per CTA in smem, K = [x(0..7) | h(8..71) | bias=1 (72) | pad(73..87)]
// B[256 x 88]: n = half*128 + gate*32 + j, gate in {r,z,nh,nx}, col = half*32+j.
// D computed per warp (rb, half): rows rb*16..+15, n-tiles t=gate*4+jt.
// 3 MMA products: Ah*Bh + Al*Bh + Ah*Bl.

#define SEQ_LEN   256
#define LABEL_LEN 128
#define BATCH     8192
#define MROWS     64
#define NCTA      (BATCH / MROWS)   // 128
#define NTH       256
#define SK        88                // k stride (bf16 elements)

struct SmemR {
    __nv_bfloat16 Bh[256 * SK];
    __nv_bfloat16 Bl[256 * SK];
    __nv_bfloat16 Ah[64 * SK];
    __nv_bfloat16 Al[64 * SK];
    float h32[64 * 65];
    float wout[64 * 8];   // [k][o]
    float bout_s[8];
};

__device__ __forceinline__ float sigf(float x) {
    return __fdividef(1.0f, 1.0f + __expf(-x));
}
__device__ __forceinline__ float tanh_(float x) {
    return __fdividef(2.0f, 1.0f + __expf(-2.0f * x)) - 1.0f;
}

// pack (a,b) -> bf16x2 (a low); *lo = residuals bf16x2
__device__ __forceinline__ uint32_t packsplit(float a, float b, uint32_t* lo) {
    __nv_bfloat16 ah = __float2bfloat16(a), bh = __float2bfloat16(b);
    __nv_bfloat16 al = __float2bfloat16(a - __bfloat162float(ah));
    __nv_bfloat16 bl = __float2bfloat16(b - __bfloat162float(bh));
    *lo = ((uint32_t)__bfloat16_as_ushort(bl) << 16) | (uint32_t)__bfloat16_as_ushort(al);
    return ((uint32_t)__bfloat16_as_ushort(bh) << 16) | (uint32_t)__bfloat16_as_ushort(ah);
}

__device__ __forceinline__ void mma16816(float* c, const uint32_t* a,
                                         uint32_t b0, uint32_t b1) {
    asm volatile(
        "mma.sync.aligned.m16n8k16.row.col.f32.bf16.bf16.f32 "
        "{%0,%1,%2,%3}, {%4,%5,%6,%7}, {%8,%9}, {%0,%1,%2,%3};"
        : "+f"(c[0]), "+f"(c[1]), "+f"(c[2]), "+f"(c[3])
        : "r"(a[0]), "r"(a[1]), "r"(a[2]), "r"(a[3]), "r"(b0), "r"(b1));
}

__device__ float bval(int n, int k, const float* Wih, const float* Whh,
                      const float* bih, const float* bhh) {
    const int half = n >> 7, g = (n >> 5) & 3, j = n & 31;
    const int col = half * 32 + j;
    if (g < 2) {                       // r or z gate
        const int G = g * 64 + col;
        if (k < 8)   return Wih[G * 8 + k];
        if (k < 72)  return Whh[G * 64 + (k - 8)];
        if (k == 72) return bih[G] + bhh[G];
        return 0.0f;
    } else if (g == 2) {               // nh
        const int G = 128 + col;
        if (k >= 8 && k < 72) return Whh[G * 64 + (k - 8)];
        if (k == 72)          return bhh[G];
        return 0.0f;
    } else {                           // nx
        const int G = 128 + col;
        if (k < 8)   return Wih[G * 8 + k];
        if (k == 72) return bih[G];
        return 0.0f;
    }
}

__device__ void build_B(SmemR* s, const float* Wih, const float* Whh,
                        const float* bih, const float* bhh) {
    const int n = threadIdx.x;         // 256 threads -> one n row each
    for (int k = 0; k < SK; k++) {
        float w = (k < 73) ? bval(n, k, Wih, Whh, bih, bhh) : 0.0f;
        __nv_bfloat16 h = __float2bfloat16(w);
        __nv_bfloat16 l = __float2bfloat16(w - __bfloat162float(h));
        s->Bh[n * SK + k] = h;
        s->Bl[n * SK + k] = l;
    }
}

// write 8 fp32 input features to A row (k=0..7), hi+lo
__device__ __forceinline__ void sts_x(SmemR* s, int row, const float* v) {
    #pragma unroll
    for (int p = 0; p < 4; p++) {
        uint32_t lo, hi = packsplit(v[2 * p], v[2 * p + 1], &lo);
        *(uint32_t*)&s->Ah[row * SK + 2 * p] = hi;
        *(uint32_t*)&s->Al[row * SK + 2 * p] = lo;
    }
}

// One GRU step: A-frag loads, internal sync, MMAs, optional x write, epilogue.
// hreg[16]: idx = jt*4 + q (q = C-fragment slot). Caller syncs after return.
__device__ __forceinline__ void gru_step(SmemR* s, int rb, int half, int g4,
                                         int tk, float* hreg, bool dec,
                                         const float* xn, bool do_x, int xrow) {
    const int r0 = rb * 16 + g4;
    const uint32_t ab0 = (uint32_t)(r0 * SK), ab8 = (uint32_t)((r0 + 8) * SK);
    const int ko = tk * 2;

    uint32_t afh[5][4], afl[5][4];
    #pragma unroll
    for (int c = 0; c < 5; c++) {
        const int k0 = c * 16 + ko;
        afh[c][0] = *(const uint32_t*)&s->Ah[ab0 + k0];
        afh[c][1] = *(const uint32_t*)&s->Ah[ab8 + k0];
        afh[c][2] = *(const uint32_t*)&s->Ah[ab0 + k0 + 8];
        afh[c][3] = *(const uint32_t*)&s->Ah[ab8 + k0 + 8];
        afl[c][0] = *(const uint32_t*)&s->Al[ab0 + k0];
        afl[c][1] = *(const uint32_t*)&s->Al[ab8 + k0];
        afl[c][2] = *(const uint32_t*)&s->Al[ab0 + k0 + 8];
        afl[c][3] = *(const uint32_t*)&s->Al[ab8 + k0 + 8];
    }
    __syncthreads();   // everyone has A; smem A is now writable

    float acc[16][4];
    #pragma unroll
    for (int t = 0; t < 16; t++)
        #pragma unroll
        for (int q = 0; q < 4; q++) acc[t][q] = 0.0f;

    const uint32_t nb = (uint32_t)((half * 128 + g4) * SK);
    #pragma unroll
    for (int t = 0; t < 16; t++) {
        const int g = t >> 2;
        const uint32_t bb = nb + (uint32_t)(t * 8 * SK);
        #pragma unroll
        for (int c = 0; c < 5; c++) {
            if (g == 3 && c != 0 && c != 4) continue;   // nx: chunks {0,4}
            const int k0 = c * 16 + ko;
            const uint32_t bh0 = *(const uint32_t*)&s->Bh[bb + k0];
            const uint32_t bh1 = *(const uint32_t*)&s->Bh[bb + k0 + 8];
            mma16816(acc[t], afh[c], bh0, bh1);
            mma16816(acc[t], afl[c], bh0, bh1);
            const uint32_t bl0 = *(const uint32_t*)&s->Bl[bb + k0];
            const uint32_t bl1 = *(const uint32_t*)&s->Bl[bb + k0 + 8];
            mma16816(acc[t], afh[c], bl0, bl1);
        }
    }

    if (do_x) sts_x(s, xrow, xn);   // LDG latency amortized behind the MMAs

    // epilogue: gates + h update + store h (bf16 hi/lo, + fp32 in decoder)
    #pragma unroll
    for (int jt = 0; jt < 4; jt++) {
        const float* cr  = acc[jt];
        const float* cz  = acc[4 + jt];
        const float* cnh = acc[8 + jt];
        const float* cnx = acc[12 + jt];
        #pragma unroll
        for (int q = 0; q < 4; q++) {
            const float r = sigf(cr[q]);
            const float z = sigf(cz[q]);
            const float n = tanh_(fmaf(r, cnh[q], cnx[q]));
            hreg[jt * 4 + q] = fmaf(z, hreg[jt * 4 + q] - n, n);
        }
        const int col0 = half * 32 + jt * 8 + ko;
        uint32_t lo0, hi0 = packsplit(hreg[jt * 4 + 0], hreg[jt * 4 + 1], &lo0);
        uint32_t lo1, hi1 = packsplit(hreg[jt * 4 + 2], hreg[jt * 4 + 3], &lo1);
        *(uint32_t*)&s->Ah[ab0 + 8 + col0] = hi0;
        *(uint32_t*)&s->Al[ab0 + 8 + col0] = lo0;
        *(uint32_t*)&s->Ah[ab8 + 8 + col0] = hi1;
        *(uint32_t*)&s->Al[ab8 + 8 + col0] = lo1;
        if (dec) {
            s->h32[r0 * 65 + col0]       = hreg[jt * 4 + 0];
            s->h32[r0 * 65 + col0 + 1]   = hreg[jt * 4 + 1];
            s->h32[(r0 + 8) * 65 + col0]     = hreg[jt * 4 + 2];
            s->h32[(r0 + 8) * 65 + col0 + 1] = hreg[jt * 4 + 3];
        }
    }
}

extern __shared__ __align__(16) char smem_raw[];

__global__ void __launch_bounds__(NTH, 1)
seq2seq_hmma_kernel(const float* __restrict__ x,  const float* __restrict__ xy,
                    const float* __restrict__ eWih, const float* __restrict__ eWhh,
                    const float* __restrict__ ebih, const float* __restrict__ ebhh,
                    const float* __restrict__ dWih, const float* __restrict__ dWhh,
                    const float* __restrict__ dbih, const float* __restrict__ dbhh,
                    const float* __restrict__ Wout, const float* __restrict__ bout,
                    float* __restrict__ out)
{
    SmemR* s = (SmemR*)smem_raw;
    const int tid  = threadIdx.x;
    const int wid  = tid >> 5;
    const int lane = tid & 31;
    const int rb   = wid & 3;
    const int half = wid >> 2;
    const int g4   = lane >> 2;
    const int tk   = lane & 3;
    const int b0   = blockIdx.x * MROWS;

    // ---- init A (zero + bias), B (encoder), Wout ----
    for (int i = tid; i < 64 * SK; i += NTH) {
        s->Ah[i] = __float2bfloat16(0.0f);
        s->Al[i] = __float2bfloat16(0.0f);
    }
    build_B(s, eWih, eWhh, ebih, ebhh);
    for (int i = tid; i < 64 * 8; i += NTH) {     // Wout [8,64] -> [k][o]
        int o = i / 64, k = i % 64;
        s->wout[k * 8 + o] = Wout[i];
    }
    if (tid < 8) s->bout_s[tid] = bout[tid];
    __syncthreads();
    if (tid < 64) {
        s->Ah[tid * SK + 72] = __float2bfloat16(1.0f);   // bias column
        float v[8];
        const float* xp = x + ((size_t)b0 + tid) * 8;    // x[0]
        float4 a = *(const float4*)xp;
        float4 b = *(const float4*)(xp + 4);
        v[0]=a.x; v[1]=a.y; v[2]=a.z; v[3]=a.w; v[4]=b.x; v[5]=b.y; v[6]=b.z; v[7]=b.w;
        sts_x(s, tid, v);
    }
    __syncthreads();

    float hreg[16];
    #pragma unroll
    for (int i = 0; i < 16; i++) hreg[i] = 0.0f;

    // =================== Encoder: 256 steps ===================
    for (int t = 0; t < SEQ_LEN; t++) {
        float xn[8];
        const bool do_x = (tid < 64);
        if (do_x) {
            const float* xp = (t + 1 < SEQ_LEN)
                ? x + (((size_t)(t + 1)) * BATCH + b0 + tid) * 8
                : xy + ((size_t)b0 + tid) * 8;
            float4 a = *(const float4*)xp;
            float4 b = *(const float4*)(xp + 4);
            xn[0]=a.x; xn[1]=a.y; xn[2]=a.z; xn[3]=a.w;
            xn[4]=b.x; xn[5]=b.y; xn[6]=b.z; xn[7]=b.w;
        }
        gru_step(s, rb, half, g4, tk, hreg, false, xn, do_x, tid);
        __syncthreads();
    }

    // ---- swap in decoder weights ----
    build_B(s, dWih, dWhh, dbih, dbhh);
    __syncthreads();

    // =================== Decoder: 128 steps ===================
    const int prow = tid >> 2;       // projection row (0..63)
    const int o2   = tid & 3;        // output pair
    for (int t = 0; t < LABEL_LEN; t++) {
        gru_step(s, rb, half, g4, tk, hreg, true, nullptr, false, 0);
        __syncthreads();             // h32 visible

        // output projection: 2 outs per thread over K=64
        float a0 = s->bout_s[2 * o2], a1 = s->bout_s[2 * o2 + 1];
        const float* hrow = &s->h32[prow * 65];
        #pragma unroll 8
        for (int k = 0; k < 64; k++) {
            const float hv = hrow[k];
            a0 = fmaf(hv, s->wout[k * 8 + 2 * o2], a0);
            a1 = fmaf(hv, s->wout[k * 8 + 2 * o2 + 1], a1);
        }
        float* op = out + (((size_t)t) * BATCH + b0 + prow) * 8 + 2 * o2;
        *(float2*)op = make_float2(a0, a1);

        // feedback as next decoder input x
        uint32_t lo, hi = packsplit(a0, a1, &lo);
        *(uint32_t*)&s->Ah[prow * SK + 2 * o2] = hi;
        *(uint32_t*)&s->Al[prow * SK + 2 * o2] = lo;
        __syncthreads();
    }
}

extern "C" void kernel_launch(void* const* d_in, const int* in_sizes, int n_in,
                              void* d_out, int out_size) {
    const float* x    = (const float*)d_in[0];
    const float* xy   = (const float*)d_in[1];
    const float* eWih = (const float*)d_in[2];
    const float* eWhh = (const float*)d_in[3];
    const float* ebih = (const float*)d_in[4];
    const float* ebhh = (const float*)d_in[5];
    const float* dWih = (const float*)d_in[6];
    const float* dWhh = (const float*)d_in[7];
    const float* dbih = (const float*)d_in[8];
    const float* dbhh = (const float*)d_in[9];
    const float* Wout = (const float*)d_in[10];
    const float* bout = (const float*)d_in[11];
    float* out = (float*)d_out;

    const int smem_bytes = (int)sizeof(SmemR);
    cudaFuncSetAttribute(seq2seq_hmma_kernel,
                         cudaFuncAttributeMaxDynamicSharedMemorySize, smem_bytes);

    seq2seq_hmma_kernel<<<NCTA, NTH, smem_bytes>>>(
        x, xy, eWih, eWhh, ebih, ebhh, dWih, dWhh, dbih, dbhh, Wout, bout, out);
}

// round 10
// speedup vs baseline: 2.5884x; 1.0125x over previous
#include <cuda_runtime.h>
#include <cuda_bf16.h>
#include <cstdint>

// Seq2Seq GRU via mma.sync bf16 (HMMA), 2-way bf16 split.
// R9: 512 threads (16 warps: rb = row-block 0..3, q = col-quarter 0..3),
//     tanh.approx activations.
// A[64 x 88] smem: K = [x(0..7) | h(8..71) | bias=1(72) | pad]
// B[256 x 88]: n = q*64 + gate*16 + jj, gate in {r,z,nh,nx}, hidden col = q*16+jj.

#define SEQ_LEN   256
#define LABEL_LEN 128
#define BATCH     8192
#define MROWS     64
#define NCTA      (BATCH / MROWS)   // 128
#define NTH       512
#define SK        88                // k stride (bf16 elements)

struct SmemR {
    __nv_bfloat16 Bh[256 * SK];
    __nv_bfloat16 Bl[256 * SK];
    __nv_bfloat16 Ah[64 * SK];
    __nv_bfloat16 Al[64 * SK];
    float h32[64 * 65];
    float wout[64 * 8];   // [k][o]
    float bout_s[8];
};

__device__ __forceinline__ float tanhapx(float x) {
    float y;
    asm("tanh.approx.f32 %0, %1;" : "=f"(y) : "f"(x));
    return y;
}
__device__ __forceinline__ float sigapx(float x) {
    return fmaf(0.5f, tanhapx(0.5f * x), 0.5f);
}

// pack (a,b) -> bf16x2 (a low); *lo = residuals bf16x2
__device__ __forceinline__ uint32_t packsplit(float a, float b, uint32_t* lo) {
    __nv_bfloat16 ah = __float2bfloat16(a), bh = __float2bfloat16(b);
    __nv_bfloat16 al = __float2bfloat16(a - __bfloat162float(ah));
    __nv_bfloat16 bl = __float2bfloat16(b - __bfloat162float(bh));
    *lo = ((uint32_t)__bfloat16_as_ushort(bl) << 16) | (uint32_t)__bfloat16_as_ushort(al);
    return ((uint32_t)__bfloat16_as_ushort(bh) << 16) | (uint32_t)__bfloat16_as_ushort(ah);
}

__device__ __forceinline__ void mma16816(float* c, const uint32_t* a,
                                         uint32_t b0, uint32_t b1) {
    asm volatile(
        "mma.sync.aligned.m16n8k16.row.col.f32.bf16.bf16.f32 "
        "{%0,%1,%2,%3}, {%4,%5,%6,%7}, {%8,%9}, {%0,%1,%2,%3};"
        : "+f"(c[0]), "+f"(c[1]), "+f"(c[2]), "+f"(c[3])
        : "r"(a[0]), "r"(a[1]), "r"(a[2]), "r"(a[3]), "r"(b0), "r"(b1));
}

// B weight for flattened row n and k. n = q*64 + g*16 + jj, hidden col = q*16+jj
__device__ float bval(int n, int k, const float* Wih, const float* Whh,
                      const float* bih, const float* bhh) {
    const int q = n >> 6, g = (n >> 4) & 3, jj = n & 15;
    const int col = q * 16 + jj;
    if (g < 2) {                       // r or z gate
        const int G = g * 64 + col;
        if (k < 8)   return Wih[G * 8 + k];
        if (k < 72)  return Whh[G * 64 + (k - 8)];
        if (k == 72) return bih[G] + bhh[G];
        return 0.0f;
    } else if (g == 2) {               // nh
        const int G = 128 + col;
        if (k >= 8 && k < 72) return Whh[G * 64 + (k - 8)];
        if (k == 72)          return bhh[G];
        return 0.0f;
    } else {                           // nx
        const int G = 128 + col;
        if (k < 8)   return Wih[G * 8 + k];
        if (k == 72) return bih[G];
        return 0.0f;
    }
}

__device__ void build_B(SmemR* s, const float* Wih, const float* Whh,
                        const float* bih, const float* bhh) {
    for (int idx = threadIdx.x; idx < 256 * SK; idx += NTH) {
        const int n = idx / SK, k = idx % SK;
        float w = (k < 73) ? bval(n, k, Wih, Whh, bih, bhh) : 0.0f;
        __nv_bfloat16 h = __float2bfloat16(w);
        __nv_bfloat16 l = __float2bfloat16(w - __bfloat162float(h));
        s->Bh[idx] = h;
        s->Bl[idx] = l;
    }
}

// write 8 fp32 input features to A row (k=0..7), hi+lo
__device__ __forceinline__ void sts_x(SmemR* s, int row, const float* v) {
    #pragma unroll
    for (int p = 0; p < 4; p++) {
        uint32_t lo, hi = packsplit(v[2 * p], v[2 * p + 1], &lo);
        *(uint32_t*)&s->Ah[row * SK + 2 * p] = hi;
        *(uint32_t*)&s->Al[row * SK + 2 * p] = lo;
    }
}

// One GRU step for warp (rb, q). hreg[8]: idx = jt*4 + cslot.
// Caller must __syncthreads() after return (before next A read).
__device__ __forceinline__ void gru_step(SmemR* s, int rb, int q, int g4,
                                         int tk, float* hreg, bool dec,
                                         const float* xn, bool do_x, int xrow) {
    const int r0 = rb * 16 + g4;
    const uint32_t ab0 = (uint32_t)(r0 * SK), ab8 = (uint32_t)((r0 + 8) * SK);
    const int ko = tk * 2;

    uint32_t afh[5][4], afl[5][4];
    #pragma unroll
    for (int c = 0; c < 5; c++) {
        const int k0 = c * 16 + ko;
        afh[c][0] = *(const uint32_t*)&s->Ah[ab0 + k0];
        afh[c][1] = *(const uint32_t*)&s->Ah[ab8 + k0];
        afh[c][2] = *(const uint32_t*)&s->Ah[ab0 + k0 + 8];
        afh[c][3] = *(const uint32_t*)&s->Ah[ab8 + k0 + 8];
        afl[c][0] = *(const uint32_t*)&s->Al[ab0 + k0];
        afl[c][1] = *(const uint32_t*)&s->Al[ab8 + k0];
        afl[c][2] = *(const uint32_t*)&s->Al[ab0 + k0 + 8];
        afl[c][3] = *(const uint32_t*)&s->Al[ab8 + k0 + 8];
    }
    __syncthreads();   // everyone has A; smem A is now writable

    float acc[8][4];
    #pragma unroll
    for (int t = 0; t < 8; t++)
        #pragma unroll
        for (int c = 0; c < 4; c++) acc[t][c] = 0.0f;

    const uint32_t nb = (uint32_t)((q * 64 + g4) * SK);
    #pragma unroll
    for (int t = 0; t < 8; t++) {
        const int g = t >> 1;
        const uint32_t bb = nb + (uint32_t)(t * 8 * SK);
        #pragma unroll
        for (int c = 0; c < 5; c++) {
            if (g == 3 && c != 0 && c != 4) continue;   // nx: chunks {0,4}
            const int k0 = c * 16 + ko;
            const uint32_t bh0 = *(const uint32_t*)&s->Bh[bb + k0];
            const uint32_t bh1 = *(const uint32_t*)&s->Bh[bb + k0 + 8];
            mma16816(acc[t], afh[c], bh0, bh1);
            mma16816(acc[t], afl[c], bh0, bh1);
            const uint32_t bl0 = *(const uint32_t*)&s->Bl[bb + k0];
            const uint32_t bl1 = *(const uint32_t*)&s->Bl[bb + k0 + 8];
            mma16816(acc[t], afh[c], bl0, bl1);
        }
    }

    if (do_x) sts_x(s, xrow, xn);   // behind the MMAs

    // epilogue: gates + h update + store h (bf16 hi/lo, + fp32 in decoder)
    #pragma unroll
    for (int jt = 0; jt < 2; jt++) {
        const float* cr  = acc[jt];
        const float* cz  = acc[2 + jt];
        const float* cnh = acc[4 + jt];
        const float* cnx = acc[6 + jt];
        #pragma unroll
        for (int c = 0; c < 4; c++) {
            const float r = sigapx(cr[c]);
            const float z = sigapx(cz[c]);
            const float n = tanhapx(fmaf(r, cnh[c], cnx[c]));
            hreg[jt * 4 + c] = fmaf(z, hreg[jt * 4 + c] - n, n);
        }
        const int col0 = q * 16 + jt * 8 + ko;
        uint32_t lo0, hi0 = packsplit(hreg[jt * 4 + 0], hreg[jt * 4 + 1], &lo0);
        uint32_t lo1, hi1 = packsplit(hreg[jt * 4 + 2], hreg[jt * 4 + 3], &lo1);
        *(uint32_t*)&s->Ah[ab0 + 8 + col0] = hi0;
        *(uint32_t*)&s->Al[ab0 + 8 + col0] = lo0;
        *(uint32_t*)&s->Ah[ab8 + 8 + col0] = hi1;
        *(uint32_t*)&s->Al[ab8 + 8 + col0] = lo1;
        if (dec) {
            s->h32[r0 * 65 + col0]           = hreg[jt * 4 + 0];
            s->h32[r0 * 65 + col0 + 1]       = hreg[jt * 4 + 1];
            s->h32[(r0 + 8) * 65 + col0]     = hreg[jt * 4 + 2];
            s->h32[(r0 + 8) * 65 + col0 + 1] = hreg[jt * 4 + 3];
        }
    }
}

extern __shared__ __align__(16) char smem_raw[];

__global__ void __launch_bounds__(NTH, 1)
seq2seq_hmma_kernel(const float* __restrict__ x,  const float* __restrict__ xy,
                    const float* __restrict__ eWih, const float* __restrict__ eWhh,
                    const float* __restrict__ ebih, const float* __restrict__ ebhh,
                    const float* __restrict__ dWih, const float* __restrict__ dWhh,
                    const float* __restrict__ dbih, const float* __restrict__ dbhh,
                    const float* __restrict__ Wout, const float* __restrict__ bout,
                    float* __restrict__ out)
{
    SmemR* s = (SmemR*)smem_raw;
    const int tid  = threadIdx.x;
    const int wid  = tid >> 5;
    const int lane = tid & 31;
    const int rb   = wid & 3;
    const int q    = wid >> 2;
    const int g4   = lane >> 2;
    const int tk   = lane & 3;
    const int b0   = blockIdx.x * MROWS;

    // ---- init A (zero + bias), B (encoder), Wout ----
    for (int i = tid; i < 64 * SK; i += NTH) {
        s->Ah[i] = __float2bfloat16(0.0f);
        s->Al[i] = __float2bfloat16(0.0f);
    }
    build_B(s, eWih, eWhh, ebih, ebhh);
    for (int i = tid; i < 64 * 8; i += NTH) {     // Wout [8,64] -> [k][o]
        int o = i / 64, k = i % 64;
        s->wout[k * 8 + o] = Wout[i];
    }
    if (tid < 8) s->bout_s[tid] = bout[tid];
    __syncthreads();
    if (tid < 64) {
        s->Ah[tid * SK + 72] = __float2bfloat16(1.0f);   // bias column
        float v[8];
        const float* xp = x + ((size_t)b0 + tid) * 8;    // x[0]
        float4 a = *(const float4*)xp;
        float4 b = *(const float4*)(xp + 4);
        v[0]=a.x; v[1]=a.y; v[2]=a.z; v[3]=a.w; v[4]=b.x; v[5]=b.y; v[6]=b.z; v[7]=b.w;
        sts_x(s, tid, v);
    }
    __syncthreads();

    float hreg[8];
    #pragma unroll
    for (int i = 0; i < 8; i++) hreg[i] = 0.0f;

    // =================== Encoder: 256 steps ===================
    for (int t = 0; t < SEQ_LEN; t++) {
        float xn[8];
        const bool do_x = (tid < 64);
        if (do_x) {
            const float* xp = (t + 1 < SEQ_LEN)
                ? x + (((size_t)(t + 1)) * BATCH + b0 + tid) * 8
                : xy + ((size_t)b0 + tid) * 8;
            float4 a = *(const float4*)xp;
            float4 b = *(const float4*)(xp + 4);
            xn[0]=a.x; xn[1]=a.y; xn[2]=a.z; xn[3]=a.w;
            xn[4]=b.x; xn[5]=b.y; xn[6]=b.z; xn[7]=b.w;
        }
        gru_step(s, rb, q, g4, tk, hreg, false, xn, do_x, tid);
        __syncthreads();
    }

    // ---- swap in decoder weights ----
    build_B(s, dWih, dWhh, dbih, dbhh);
    __syncthreads();

    // =================== Decoder: 128 steps ===================
    const int prow = tid >> 3;       // projection row (0..63)
    const int o    = tid & 7;        // output index
    for (int t = 0; t < LABEL_LEN; t++) {
        gru_step(s, rb, q, g4, tk, hreg, true, nullptr, false, 0);
        __syncthreads();             // h32 visible

        // output projection: 1 out per thread over K=64
        float a0 = s->bout_s[o];
        const float* hrow = &s->h32[prow * 65];
        #pragma unroll 8
        for (int k = 0; k < 64; k++)
            a0 = fmaf(hrow[k], s->wout[k * 8 + o], a0);

        out[(((size_t)t) * BATCH + b0 + prow) * 8 + o] = a0;

        // feedback as next decoder input x (single bf16 hi + residual lo)
        __nv_bfloat16 h = __float2bfloat16(a0);
        s->Ah[prow * SK + o] = h;
        s->Al[prow * SK + o] = __float2bfloat16(a0 - __bfloat162float(h));
        __syncthreads();
    }
}

extern "C" void kernel_launch(void* const* d_in, const int* in_sizes, int n_in,
                              void* d_out, int out_size) {
    const float* x    = (const float*)d_in[0];
    const float* xy   = (const float*)d_in[1];
    const float* eWih = (const float*)d_in[2];
    const float* eWhh = (const float*)d_in[3];
    const float* ebih = (const float*)d_in[4];
    const float* ebhh = (const float*)d_in[5];
    const float* dWih = (const float*)d_in[6];
    const float* dWhh = (const float*)d_in[7];
    const float* dbih = (const float*)d_in[8];
    const float* dbhh = (const float*)d_in[9];
    const float* Wout = (const float*)d_in[10];
    const float* bout = (const float*)d_in[11];
    float* out = (float*)d_out;

    const int smem_bytes = (int)sizeof(SmemR);
    cudaFuncSetAttribute(seq2seq_hmma_kernel,
                         cudaFuncAttributeMaxDynamicSharedMemorySize, smem_bytes);

    seq2seq_hmma_kernel<<<NCTA, NTH, smem_bytes>>>(
        x, xy, eWih, eWhh, ebih, ebhh, dWih, dWhh, dbih, dbhh, Wout, bout, out);
}

// round 11
// speedup vs baseline: 2.8508x; 1.1014x over previous
#include <cuda_runtime.h>
#include <cuda_bf16.h>
#include <cstdint>

// Seq2Seq GRU via mma.sync bf16 (HMMA), 2-way bf16 split.
// R10: fragment-permuted B (LDS.128 groups) + fragment-permuted double-buffered A
//      (1 sync/step in encoder). 512 threads: warp = (rb 0..3, q 0..3).
// Logical A[64 x 80]: K = [x(0..7) | h(8..71) | bias=1(72) | pad..79]
// Logical B[256 x 80]: n = q*64 + t*8 + g4 -> gate g=t>>1 in {r,z,nh,nx}, col q*16+(t&1)*8+..

#define SEQ_LEN   256
#define LABEL_LEN 128
#define BATCH     8192
#define MROWS     64
#define NCTA      (BATCH / MROWS)   // 128
#define NTH       512

#define PB_STRIDE 140    // u32 per warp-thread (34 groups * 4, padded from 136)
#define PA_STRIDE 44     // u32 per thread-slot (5 chunks * 8, padded from 40)

struct SmemR {
    uint32_t PB[128 * PB_STRIDE];      // permuted B: [qgt][gi*4 + {bh0,bh1,bl0,bl1}]
    uint32_t PA[2][128 * PA_STRIDE];   // permuted A: [buf][rgt][c*8 + {hi0..3, lo0..3}]
    float h32[64 * 65];
    float wout[64 * 8];                // [k][o]
    float bout_s[8];
};

__device__ __forceinline__ float tanhapx(float x) {
    float y;
    asm("tanh.approx.f32 %0, %1;" : "=f"(y) : "f"(x));
    return y;
}
__device__ __forceinline__ float sigapx(float x) {
    return fmaf(0.5f, tanhapx(0.5f * x), 0.5f);
}

// pack (a,b) -> bf16x2 (a low); *lo = residuals bf16x2
__device__ __forceinline__ uint32_t packsplit(float a, float b, uint32_t* lo) {
    __nv_bfloat16 ah = __float2bfloat16(a), bh = __float2bfloat16(b);
    __nv_bfloat16 al = __float2bfloat16(a - __bfloat162float(ah));
    __nv_bfloat16 bl = __float2bfloat16(b - __bfloat162float(bh));
    *lo = ((uint32_t)__bfloat16_as_ushort(bl) << 16) | (uint32_t)__bfloat16_as_ushort(al);
    return ((uint32_t)__bfloat16_as_ushort(bh) << 16) | (uint32_t)__bfloat16_as_ushort(ah);
}

__device__ __forceinline__ void mma16816(float* c, const uint32_t* a,
                                         uint32_t b0, uint32_t b1) {
    asm volatile(
        "mma.sync.aligned.m16n8k16.row.col.f32.bf16.bf16.f32 "
        "{%0,%1,%2,%3}, {%4,%5,%6,%7}, {%8,%9}, {%0,%1,%2,%3};"
        : "+f"(c[0]), "+f"(c[1]), "+f"(c[2]), "+f"(c[3])
        : "r"(a[0]), "r"(a[1]), "r"(a[2]), "r"(a[3]), "r"(b0), "r"(b1));
}

// B weight for flattened n = q*64 + g*16 + jj (hidden col q*16+jj), k in 0..72
__device__ float bval(int n, int k, const float* Wih, const float* Whh,
                      const float* bih, const float* bhh) {
    if (k >= 73) return 0.0f;
    const int q = n >> 6, g = (n >> 4) & 3, jj = n & 15;
    const int col = q * 16 + jj;
    if (g < 2) {                       // r or z gate
        const int G = g * 64 + col;
        if (k < 8)   return Wih[G * 8 + k];
        if (k < 72)  return Whh[G * 64 + (k - 8)];
        return bih[G] + bhh[G];        // k == 72
    } else if (g == 2) {               // nh
        const int G = 128 + col;
        if (k >= 8 && k < 72) return Whh[G * 64 + (k - 8)];
        if (k == 72)          return bhh[G];
        return 0.0f;
    } else {                           // nx
        const int G = 128 + col;
        if (k < 8)   return Wih[G * 8 + k];
        if (k == 72) return bih[G];
        return 0.0f;
    }
}

// Build fragment-permuted B. group gi order must match consumption in gru_step:
// gi<30: t=gi/5, c=gi%5; else t=6+(gi-30)/2, c=((gi-30)&1)*4.
__device__ void build_PB(SmemR* s, const float* Wih, const float* Whh,
                         const float* bih, const float* bhh) {
    for (int idx = threadIdx.x; idx < 128 * 34; idx += NTH) {
        const int qgt = idx / 34, gi = idx % 34;
        const int q = qgt >> 5, g4 = (qgt >> 2) & 7, tk = qgt & 3;
        int t, c;
        if (gi < 30) { t = gi / 5; c = gi % 5; }
        else { const int g2 = gi - 30; t = 6 + (g2 >> 1); c = (g2 & 1) * 4; }
        const int n  = q * 64 + t * 8 + g4;
        const int k0 = c * 16 + tk * 2;
        uint32_t l0, h0 = packsplit(bval(n, k0,     Wih, Whh, bih, bhh),
                                    bval(n, k0 + 1, Wih, Whh, bih, bhh), &l0);
        uint32_t l1, h1 = packsplit(bval(n, k0 + 8, Wih, Whh, bih, bhh),
                                    bval(n, k0 + 9, Wih, Whh, bih, bhh), &l1);
        uint32_t* p = &s->PB[qgt * PB_STRIDE + gi * 4];
        p[0] = h0; p[1] = h1; p[2] = l0; p[3] = l1;
    }
}

// x-thread (row = tid < 64) writes 8 input features into PA[buf] (c=0 region)
__device__ __forceinline__ void write_x(SmemR* s, int buf, int row, const float* v) {
    const int rb = row >> 4, g4 = row & 7, rh = (row >> 3) & 1;
    #pragma unroll
    for (int p = 0; p < 4; p++) {
        uint32_t lo, hi = packsplit(v[2 * p], v[2 * p + 1], &lo);
        uint32_t* d = &s->PA[buf][((rb * 8 + g4) * 4 + p) * PA_STRIDE];
        d[rh]     = hi;
        d[4 + rh] = lo;
    }
}

extern __shared__ __align__(16) char smem_raw[];

__global__ void __launch_bounds__(NTH, 1)
seq2seq_hmma_kernel(const float* __restrict__ x,  const float* __restrict__ xy,
                    const float* __restrict__ eWih, const float* __restrict__ eWhh,
                    const float* __restrict__ ebih, const float* __restrict__ ebhh,
                    const float* __restrict__ dWih, const float* __restrict__ dWhh,
                    const float* __restrict__ dbih, const float* __restrict__ dbhh,
                    const float* __restrict__ Wout, const float* __restrict__ bout,
                    float* __restrict__ out)
{
    SmemR* s = (SmemR*)smem_raw;
    const int tid  = threadIdx.x;
    const int wid  = tid >> 5;
    const int lane = tid & 31;
    const int rb   = wid & 3;
    const int q    = wid >> 2;
    const int g4   = lane >> 2;
    const int tk   = lane & 3;
    const int b0   = blockIdx.x * MROWS;
    const int rgt  = (rb * 8 + g4) * 4 + tk;
    const int qgt  = (q * 8 + g4) * 4 + tk;
    const int r0   = rb * 16 + g4;

    // ---- init: zero PA (both buffers), build encoder PB, Wout ----
    for (int i = tid; i < 2 * 128 * PA_STRIDE; i += NTH) s->PA[0][i] = 0u;
    build_PB(s, eWih, eWhh, ebih, ebhh);
    for (int i = tid; i < 64 * 8; i += NTH) {     // Wout [8,64] -> [k][o]
        int o = i / 64, k = i % 64;
        s->wout[k * 8 + o] = Wout[i];
    }
    if (tid < 8) s->bout_s[tid] = bout[tid];
    __syncthreads();
    if (tid < 64) {
        const int xrb = tid >> 4, xg4 = tid & 7, xrh = (tid >> 3) & 1;
        const int bbase = ((xrb * 8 + xg4) * 4 + 0) * PA_STRIDE;
        // bias column k=72: c=4, k_local=8 -> tk_c=0, slot 2+rh; word (1.0, 0.0)
        s->PA[0][bbase + 32 + 2 + xrh] = 0x00003F80u;
        s->PA[1][bbase + 32 + 2 + xrh] = 0x00003F80u;
        float v[8];
        const float* xp = x + ((size_t)b0 + tid) * 8;    // x[0]
        float4 a = *(const float4*)xp;
        float4 b = *(const float4*)(xp + 4);
        v[0]=a.x; v[1]=a.y; v[2]=a.z; v[3]=a.w; v[4]=b.x; v[5]=b.y; v[6]=b.z; v[7]=b.w;
        write_x(s, 0, tid, v);
    }
    __syncthreads();

    float hreg[8];
    #pragma unroll
    for (int i = 0; i < 8; i++) hreg[i] = 0.0f;

    int cur = 0;

    // ======================= Encoder: 256 steps =======================
    for (int t = 0; t < SEQ_LEN; t++) {
        // prefetch next input early (DRAM latency hidden behind MMAs)
        float xn[8];
        const bool do_x = (tid < 64);
        if (do_x) {
            const float* xp = (t + 1 < SEQ_LEN)
                ? x + (((size_t)(t + 1)) * BATCH + b0 + tid) * 8
                : xy + ((size_t)b0 + tid) * 8;
            float4 a = *(const float4*)xp;
            float4 b = *(const float4*)(xp + 4);
            xn[0]=a.x; xn[1]=a.y; xn[2]=a.z; xn[3]=a.w;
            xn[4]=b.x; xn[5]=b.y; xn[6]=b.z; xn[7]=b.w;
        }

        // A fragments: 10 x LDS.128
        const uint32_t* pa = &s->PA[cur][rgt * PA_STRIDE];
        uint4 AH[5], AL[5];
        #pragma unroll
        for (int c = 0; c < 5; c++) {
            AH[c] = *(const uint4*)(pa + c * 8);
            AL[c] = *(const uint4*)(pa + c * 8 + 4);
        }

        // MMA phase: 34 x LDS.128 + 102 HMMA
        float acc[8][4];
        #pragma unroll
        for (int tt = 0; tt < 8; tt++)
            #pragma unroll
            for (int cc = 0; cc < 4; cc++) acc[tt][cc] = 0.0f;

        const uint32_t* pb = &s->PB[qgt * PB_STRIDE];
        int gi = 0;
        #pragma unroll
        for (int tt = 0; tt < 8; tt++) {
            const int nc = (tt < 6) ? 5 : 2;
            #pragma unroll
            for (int ci = 0; ci < nc; ci++) {
                const int c = (tt < 6) ? ci : ci * 4;
                const uint4 bb = *(const uint4*)(pb + gi * 4);
                gi++;
                mma16816(acc[tt], (const uint32_t*)&AH[c], bb.x, bb.y);
                mma16816(acc[tt], (const uint32_t*)&AL[c], bb.x, bb.y);
                mma16816(acc[tt], (const uint32_t*)&AH[c], bb.z, bb.w);
            }
        }

        const int nxt = cur ^ 1;
        if (do_x) write_x(s, nxt, tid, xn);

        // epilogue: gates + h update + fragment-order store into PA[nxt]
        #pragma unroll
        for (int jt = 0; jt < 2; jt++) {
            const float* cr  = acc[jt];
            const float* cz  = acc[2 + jt];
            const float* cnh = acc[4 + jt];
            const float* cnx = acc[6 + jt];
            #pragma unroll
            for (int c = 0; c < 4; c++) {
                const float r = sigapx(cr[c]);
                const float z = sigapx(cz[c]);
                const float n = tanhapx(fmaf(r, cnh[c], cnx[c]));
                hreg[jt * 4 + c] = fmaf(z, hreg[jt * 4 + c] - n, n);
            }
            const int k_abs = 8 + q * 16 + jt * 8 + tk * 2;
            const int c4 = k_abs >> 4, kl = k_abs & 15;
            const int tkc = (kl & 7) >> 1, kb8 = (kl >> 3) & 1;
            uint32_t lo0, hi0 = packsplit(hreg[jt * 4 + 0], hreg[jt * 4 + 1], &lo0);
            uint32_t lo1, hi1 = packsplit(hreg[jt * 4 + 2], hreg[jt * 4 + 3], &lo1);
            uint32_t* d = &s->PA[nxt][((rb * 8 + g4) * 4 + tkc) * PA_STRIDE
                                      + c4 * 8 + kb8 * 2];
            *(uint2*)d       = make_uint2(hi0, hi1);
            *(uint2*)(d + 4) = make_uint2(lo0, lo1);
        }
        __syncthreads();
        cur ^= 1;
    }

    // ---- swap in decoder weights ----
    build_PB(s, dWih, dWhh, dbih, dbhh);
    __syncthreads();

    // ======================= Decoder: 128 steps =======================
    const int prow = tid >> 3;       // projection row (0..63)
    const int o    = tid & 7;        // output index
    for (int t = 0; t < LABEL_LEN; t++) {
        const uint32_t* pa = &s->PA[cur][rgt * PA_STRIDE];
        uint4 AH[5], AL[5];
        #pragma unroll
        for (int c = 0; c < 5; c++) {
            AH[c] = *(const uint4*)(pa + c * 8);
            AL[c] = *(const uint4*)(pa + c * 8 + 4);
        }

        float acc[8][4];
        #pragma unroll
        for (int tt = 0; tt < 8; tt++)
            #pragma unroll
            for (int cc = 0; cc < 4; cc++) acc[tt][cc] = 0.0f;

        const uint32_t* pb = &s->PB[qgt * PB_STRIDE];
        int gi = 0;
        #pragma unroll
        for (int tt = 0; tt < 8; tt++) {
            const int nc = (tt < 6) ? 5 : 2;
            #pragma unroll
            for (int ci = 0; ci < nc; ci++) {
                const int c = (tt < 6) ? ci : ci * 4;
                const uint4 bb = *(const uint4*)(pb + gi * 4);
                gi++;
                mma16816(acc[tt], (const uint32_t*)&AH[c], bb.x, bb.y);
                mma16816(acc[tt], (const uint32_t*)&AL[c], bb.x, bb.y);
                mma16816(acc[tt], (const uint32_t*)&AH[c], bb.z, bb.w);
            }
        }

        const int nxt = cur ^ 1;
        #pragma unroll
        for (int jt = 0; jt < 2; jt++) {
            const float* cr  = acc[jt];
            const float* cz  = acc[2 + jt];
            const float* cnh = acc[4 + jt];
            const float* cnx = acc[6 + jt];
            #pragma unroll
            for (int c = 0; c < 4; c++) {
                const float r = sigapx(cr[c]);
                const float z = sigapx(cz[c]);
                const float n = tanhapx(fmaf(r, cnh[c], cnx[c]));
                hreg[jt * 4 + c] = fmaf(z, hreg[jt * 4 + c] - n, n);
            }
            const int k_abs = 8 + q * 16 + jt * 8 + tk * 2;
            const int c4 = k_abs >> 4, kl = k_abs & 15;
            const int tkc = (kl & 7) >> 1, kb8 = (kl >> 3) & 1;
            uint32_t lo0, hi0 = packsplit(hreg[jt * 4 + 0], hreg[jt * 4 + 1], &lo0);
            uint32_t lo1, hi1 = packsplit(hreg[jt * 4 + 2], hreg[jt * 4 + 3], &lo1);
            uint32_t* d = &s->PA[nxt][((rb * 8 + g4) * 4 + tkc) * PA_STRIDE
                                      + c4 * 8 + kb8 * 2];
            *(uint2*)d       = make_uint2(hi0, hi1);
            *(uint2*)(d + 4) = make_uint2(lo0, lo1);
            // fp32 h for the output projection
            const int col0 = q * 16 + jt * 8 + tk * 2;
            s->h32[r0 * 65 + col0]           = hreg[jt * 4 + 0];
            s->h32[r0 * 65 + col0 + 1]       = hreg[jt * 4 + 1];
            s->h32[(r0 + 8) * 65 + col0]     = hreg[jt * 4 + 2];
            s->h32[(r0 + 8) * 65 + col0 + 1] = hreg[jt * 4 + 3];
        }
        __syncthreads();             // h32 + PA[nxt] h-words visible

        // output projection: 1 out per thread over K=64
        float a0 = s->bout_s[o];
        const float* hrow = &s->h32[prow * 65];
        #pragma unroll 8
        for (int k = 0; k < 64; k++)
            a0 = fmaf(hrow[k], s->wout[k * 8 + o], a0);

        out[(((size_t)t) * BATCH + b0 + prow) * 8 + o] = a0;

        // feedback as next decoder input x: k = o -> word pair p = o>>1, half o&1
        {
            const int frb = prow >> 4, fg4 = prow & 7, frh = (prow >> 3) & 1;
            const int base = ((frb * 8 + fg4) * 4 + (o >> 1)) * PA_STRIDE;
            __nv_bfloat16 hb = __float2bfloat16(a0);
            __nv_bfloat16 lb = __float2bfloat16(a0 - __bfloat162float(hb));
            ((__nv_bfloat16*)&s->PA[nxt][base + frh])[o & 1]     = hb;
            ((__nv_bfloat16*)&s->PA[nxt][base + 4 + frh])[o & 1] = lb;
        }
        __syncthreads();
        cur ^= 1;
    }
}

extern "C" void kernel_launch(void* const* d_in, const int* in_sizes, int n_in,
                              void* d_out, int out_size) {
    const float* x    = (const float*)d_in[0];
    const float* xy   = (const float*)d_in[1];
    const float* eWih = (const float*)d_in[2];
    const float* eWhh = (const float*)d_in[3];
    const float* ebih = (const float*)d_in[4];
    const float* ebhh = (const float*)d_in[5];
    const float* dWih = (const float*)d_in[6];
    const float* dWhh = (const float*)d_in[7];
    const float* dbih = (const float*)d_in[8];
    const float* dbhh = (const float*)d_in[9];
    const float* Wout = (const float*)d_in[10];
    const float* bout = (const float*)d_in[11];
    float* out = (float*)d_out;

    const int smem_bytes = (int)sizeof(SmemR);
    cudaFuncSetAttribute(seq2seq_hmma_kernel,
                         cudaFuncAttributeMaxDynamicSharedMemorySize, smem_bytes);

    seq2seq_hmma_kernel<<<NCTA, NTH, smem_bytes>>>(
        x, xy, eWih, eWhh, ebih, ebhh, dWih, dWhh, dbih, dbhh, Wout, bout, out);
}

// round 13
// speedup vs baseline: 2.8515x; 1.0002x over previous
#include <cuda_runtime.h>
#include <cuda_bf16.h>
#include <cstdint>

// Seq2Seq GRU via mma.sync bf16 (HMMA), 2-way bf16 split.
// R11: 8 warps (R=2 row-splits x C=4 col-quarters); each warp does 2 m16 tiles,
//      so each B fragment load feeds 6 MMAs. B smem traffic halves vs R10.
// Logical A[64 x 80]: K = [x(0..7) | h(8..71) | bias=1(72) | pad..79]
// B rows: n = q*64 + t*8 + g4, gate g=t>>1 in {r,z,nh,nx}.

#define SEQ_LEN   256
#define LABEL_LEN 128
#define BATCH     8192
#define MROWS     64
#define NCTA      (BATCH / MROWS)   // 128
#define NTH       256

#define PB_STRIDE 140    // u32 per qgt slot (34 groups * 4, padded)
#define PA_STRIDE 44     // u32 per rgt slot (5 chunks * 8, padded)

struct SmemR {
    uint32_t PB[128 * PB_STRIDE];      // permuted B: [qgt][gi*4 + {bh0,bh1,bl0,bl1}]
    uint32_t PA[2][128 * PA_STRIDE];   // permuted A: [buf][rgt][c*8 + {hi0..3, lo0..3}]
    float h32[64 * 65];
    float wout[64 * 8];                // [k][o]
    float bout_s[8];
};

__device__ __forceinline__ float tanhapx(float x) {
    float y;
    asm("tanh.approx.f32 %0, %1;" : "=f"(y) : "f"(x));
    return y;
}
__device__ __forceinline__ float sigapx(float x) {
    return fmaf(0.5f, tanhapx(0.5f * x), 0.5f);
}

// pack (a,b) -> bf16x2 (a low); *lo = residuals bf16x2
__device__ __forceinline__ uint32_t packsplit(float a, float b, uint32_t* lo) {
    __nv_bfloat16 ah = __float2bfloat16(a), bh = __float2bfloat16(b);
    __nv_bfloat16 al = __float2bfloat16(a - __bfloat162float(ah));
    __nv_bfloat16 bl = __float2bfloat16(b - __bfloat162float(bh));
    *lo = ((uint32_t)__bfloat16_as_ushort(bl) << 16) | (uint32_t)__bfloat16_as_ushort(al);
    return ((uint32_t)__bfloat16_as_ushort(bh) << 16) | (uint32_t)__bfloat16_as_ushort(ah);
}

__device__ __forceinline__ void mma16816(float* c, const uint32_t* a,
                                         uint32_t b0, uint32_t b1) {
    asm volatile(
        "mma.sync.aligned.m16n8k16.row.col.f32.bf16.bf16.f32 "
        "{%0,%1,%2,%3}, {%4,%5,%6,%7}, {%8,%9}, {%0,%1,%2,%3};"
        : "+f"(c[0]), "+f"(c[1]), "+f"(c[2]), "+f"(c[3])
        : "r"(a[0]), "r"(a[1]), "r"(a[2]), "r"(a[3]), "r"(b0), "r"(b1));
}

// B weight for flattened n = q*64 + g*16 + jj (hidden col q*16+jj), k in 0..72
__device__ float bval(int n, int k, const float* Wih, const float* Whh,
                      const float* bih, const float* bhh) {
    if (k >= 73) return 0.0f;
    const int q = n >> 6, g = (n >> 4) & 3, jj = n & 15;
    const int col = q * 16 + jj;
    if (g < 2) {                       // r or z gate
        const int G = g * 64 + col;
        if (k < 8)   return Wih[G * 8 + k];
        if (k < 72)  return Whh[G * 64 + (k - 8)];
        return bih[G] + bhh[G];        // k == 72
    } else if (g == 2) {               // nh
        const int G = 128 + col;
        if (k >= 8 && k < 72) return Whh[G * 64 + (k - 8)];
        if (k == 72)          return bhh[G];
        return 0.0f;
    } else {                           // nx
        const int G = 128 + col;
        if (k < 8)   return Wih[G * 8 + k];
        if (k == 72) return bih[G];
        return 0.0f;
    }
}

// Build fragment-permuted B. Group order matches consumption:
// gi<30: t=gi/5, c=gi%5; else t=6+(gi-30)/2, c=((gi-30)&1)*4.
__device__ void build_PB(SmemR* s, const float* Wih, const float* Whh,
                         const float* bih, const float* bhh) {
    for (int idx = threadIdx.x; idx < 128 * 34; idx += NTH) {
        const int qgt = idx / 34, gi = idx % 34;
        const int q = qgt >> 5, g4 = (qgt >> 2) & 7, tk = qgt & 3;
        int t, c;
        if (gi < 30) { t = gi / 5; c = gi % 5; }
        else { const int g2 = gi - 30; t = 6 + (g2 >> 1); c = (g2 & 1) * 4; }
        const int n  = q * 64 + t * 8 + g4;
        const int k0 = c * 16 + tk * 2;
        uint32_t l0, h0 = packsplit(bval(n, k0,     Wih, Whh, bih, bhh),
                                    bval(n, k0 + 1, Wih, Whh, bih, bhh), &l0);
        uint32_t l1, h1 = packsplit(bval(n, k0 + 8, Wih, Whh, bih, bhh),
                                    bval(n, k0 + 9, Wih, Whh, bih, bhh), &l1);
        uint32_t* p = &s->PB[qgt * PB_STRIDE + gi * 4];
        p[0] = h0; p[1] = h1; p[2] = l0; p[3] = l1;
    }
}

// x-thread (row = tid < 64) writes 8 input features into PA[buf] (c=0 region)
__device__ __forceinline__ void write_x(SmemR* s, int buf, int row, const float* v) {
    const int rt4 = row >> 4, g4 = row & 7, rh = (row >> 3) & 1;
    #pragma unroll
    for (int p = 0; p < 4; p++) {
        uint32_t lo, hi = packsplit(v[2 * p], v[2 * p + 1], &lo);
        uint32_t* d = &s->PA[buf][((rt4 * 8 + g4) * 4 + p) * PA_STRIDE];
        d[rh]     = hi;
        d[4 + rh] = lo;
    }
}

extern __shared__ __align__(16) char smem_raw[];

__global__ void __launch_bounds__(NTH, 1)
seq2seq_hmma_kernel(const float* __restrict__ x,  const float* __restrict__ xy,
                    const float* __restrict__ eWih, const float* __restrict__ eWhh,
                    const float* __restrict__ ebih, const float* __restrict__ ebhh,
                    const float* __restrict__ dWih, const float* __restrict__ dWhh,
                    const float* __restrict__ dbih, const float* __restrict__ dbhh,
                    const float* __restrict__ Wout, const float* __restrict__ bout,
                    float* __restrict__ out)
{
    SmemR* s = (SmemR*)smem_raw;
    const int tid  = threadIdx.x;
    const int wid  = tid >> 5;
    const int lane = tid & 31;
    const int q    = wid >> 1;        // col quarter 0..3
    const int rb2  = wid & 1;         // row half 0..1 (rows rb2*32 .. +31)
    const int g4   = lane >> 2;
    const int tk   = lane & 3;
    const int b0   = blockIdx.x * MROWS;
    const int qgt  = (q * 8 + g4) * 4 + tk;
    // A slots for this warp's two m16 tiles
    const int rgt0 = ((rb2 * 2 + 0) * 8 + g4) * 4 + tk;
    const int rgt1 = ((rb2 * 2 + 1) * 8 + g4) * 4 + tk;

    // ---- init: zero PA (both buffers), build encoder PB, Wout ----
    for (int i = tid; i < 2 * 128 * PA_STRIDE; i += NTH) s->PA[0][i] = 0u;
    build_PB(s, eWih, eWhh, ebih, ebhh);
    for (int i = tid; i < 64 * 8; i += NTH) {     // Wout [8,64] -> [k][o]
        int o = i / 64, k = i % 64;
        s->wout[k * 8 + o] = Wout[i];
    }
    if (tid < 8) s->bout_s[tid] = bout[tid];
    __syncthreads();
    if (tid < 64) {
        const int xrt = tid >> 4, xg4 = tid & 7, xrh = (tid >> 3) & 1;
        const int bbase = ((xrt * 8 + xg4) * 4 + 0) * PA_STRIDE;
        // bias column k=72: chunk c=4, k_local=8 -> slot word 2+rh; value (1.0,0.0)
        s->PA[0][bbase + 32 + 2 + xrh] = 0x00003F80u;
        s->PA[1][bbase + 32 + 2 + xrh] = 0x00003F80u;
        float v[8];
        const float* xp = x + ((size_t)b0 + tid) * 8;    // x[0]
        float4 a = *(const float4*)xp;
        float4 b = *(const float4*)(xp + 4);
        v[0]=a.x; v[1]=a.y; v[2]=a.z; v[3]=a.w; v[4]=b.x; v[5]=b.y; v[6]=b.z; v[7]=b.w;
        write_x(s, 0, tid, v);
    }
    __syncthreads();

    float hreg[2][8];          // [mt][jt*4 + cslot]
    #pragma unroll
    for (int m = 0; m < 2; m++)
        #pragma unroll
        for (int i = 0; i < 8; i++) hreg[m][i] = 0.0f;

    int cur = 0;

    // ======================= Encoder: 256 steps =======================
    for (int t = 0; t < SEQ_LEN; t++) {
        float xn[8];
        const bool do_x = (tid < 64);
        if (do_x) {
            const float* xp = (t + 1 < SEQ_LEN)
                ? x + (((size_t)(t + 1)) * BATCH + b0 + tid) * 8
                : xy + ((size_t)b0 + tid) * 8;
            float4 a = *(const float4*)xp;
            float4 b = *(const float4*)(xp + 4);
            xn[0]=a.x; xn[1]=a.y; xn[2]=a.z; xn[3]=a.w;
            xn[4]=b.x; xn[5]=b.y; xn[6]=b.z; xn[7]=b.w;
        }

        // A fragments for both m-tiles: 20 x LDS.128
        uint4 AH[2][5], AL[2][5];
        {
            const uint32_t* pa0 = &s->PA[cur][rgt0 * PA_STRIDE];
            const uint32_t* pa1 = &s->PA[cur][rgt1 * PA_STRIDE];
            #pragma unroll
            for (int c = 0; c < 5; c++) {
                AH[0][c] = *(const uint4*)(pa0 + c * 8);
                AL[0][c] = *(const uint4*)(pa0 + c * 8 + 4);
                AH[1][c] = *(const uint4*)(pa1 + c * 8);
                AL[1][c] = *(const uint4*)(pa1 + c * 8 + 4);
            }
        }

        // MMA phase: 34 x LDS.128, each feeding 6 MMAs (2 m-tiles x 3 products)
        float acc[2][8][4];
        #pragma unroll
        for (int m = 0; m < 2; m++)
            #pragma unroll
            for (int tt = 0; tt < 8; tt++)
                #pragma unroll
                for (int cc = 0; cc < 4; cc++) acc[m][tt][cc] = 0.0f;

        const uint32_t* pb = &s->PB[qgt * PB_STRIDE];
        int gi = 0;
        #pragma unroll
        for (int tt = 0; tt < 8; tt++) {
            const int nc = (tt < 6) ? 5 : 2;
            #pragma unroll
            for (int ci = 0; ci < nc; ci++) {
                const int c = (tt < 6) ? ci : ci * 4;
                const uint4 bb = *(const uint4*)(pb + gi * 4);
                gi++;
                mma16816(acc[0][tt], (const uint32_t*)&AH[0][c], bb.x, bb.y);
                mma16816(acc[1][tt], (const uint32_t*)&AH[1][c], bb.x, bb.y);
                mma16816(acc[0][tt], (const uint32_t*)&AL[0][c], bb.x, bb.y);
                mma16816(acc[1][tt], (const uint32_t*)&AL[1][c], bb.x, bb.y);
                mma16816(acc[0][tt], (const uint32_t*)&AH[0][c], bb.z, bb.w);
                mma16816(acc[1][tt], (const uint32_t*)&AH[1][c], bb.z, bb.w);
            }
        }

        const int nxt = cur ^ 1;
        if (do_x) write_x(s, nxt, tid, xn);

        // epilogue: gates + h update + fragment-order store into PA[nxt]
        #pragma unroll
        for (int m = 0; m < 2; m++) {
            #pragma unroll
            for (int jt = 0; jt < 2; jt++) {
                const float* cr  = acc[m][jt];
                const float* cz  = acc[m][2 + jt];
                const float* cnh = acc[m][4 + jt];
                const float* cnx = acc[m][6 + jt];
                float* hr = &hreg[m][jt * 4];
                #pragma unroll
                for (int c = 0; c < 4; c++) {
                    const float r = sigapx(cr[c]);
                    const float z = sigapx(cz[c]);
                    const float n = tanhapx(fmaf(r, cnh[c], cnx[c]));
                    hr[c] = fmaf(z, hr[c] - n, n);
                }
                const int k_abs = 8 + q * 16 + jt * 8 + tk * 2;
                const int c4 = k_abs >> 4, kl = k_abs & 15;
                const int tkc = (kl & 7) >> 1, kb8 = (kl >> 3) & 1;
                uint32_t lo0, hi0 = packsplit(hr[0], hr[1], &lo0);
                uint32_t lo1, hi1 = packsplit(hr[2], hr[3], &lo1);
                uint32_t* d = &s->PA[nxt][(((rb2 * 2 + m) * 8 + g4) * 4 + tkc) * PA_STRIDE
                                          + c4 * 8 + kb8 * 2];
                *(uint2*)d       = make_uint2(hi0, hi1);
                *(uint2*)(d + 4) = make_uint2(lo0, lo1);
            }
        }
        __syncthreads();
        cur ^= 1;
    }

    // ---- swap in decoder weights ----
    build_PB(s, dWih, dWhh, dbih, dbhh);
    __syncthreads();

    // ======================= Decoder: 128 steps =======================
    const int prow = tid >> 2;       // projection row (0..63)
    const int o2   = tid & 3;        // output pair index
    for (int t = 0; t < LABEL_LEN; t++) {
        uint4 AH[2][5], AL[2][5];
        {
            const uint32_t* pa0 = &s->PA[cur][rgt0 * PA_STRIDE];
            const uint32_t* pa1 = &s->PA[cur][rgt1 * PA_STRIDE];
            #pragma unroll
            for (int c = 0; c < 5; c++) {
                AH[0][c] = *(const uint4*)(pa0 + c * 8);
                AL[0][c] = *(const uint4*)(pa0 + c * 8 + 4);
                AH[1][c] = *(const uint4*)(pa1 + c * 8);
                AL[1][c] = *(const uint4*)(pa1 + c * 8 + 4);
            }
        }

        float acc[2][8][4];
        #pragma unroll
        for (int m = 0; m < 2; m++)
            #pragma unroll
            for (int tt = 0; tt < 8; tt++)
                #pragma unroll
                for (int cc = 0; cc < 4; cc++) acc[m][tt][cc] = 0.0f;

        const uint32_t* pb = &s->PB[qgt * PB_STRIDE];
        int gi = 0;
        #pragma unroll
        for (int tt = 0; tt < 8; tt++) {
            const int nc = (tt < 6) ? 5 : 2;
            #pragma unroll
            for (int ci = 0; ci < nc; ci++) {
                const int c = (tt < 6) ? ci : ci * 4;
                const uint4 bb = *(const uint4*)(pb + gi * 4);
                gi++;
                mma16816(acc[0][tt], (const uint32_t*)&AH[0][c], bb.x, bb.y);
                mma16816(acc[1][tt], (const uint32_t*)&AH[1][c], bb.x, bb.y);
                mma16816(acc[0][tt], (const uint32_t*)&AL[0][c], bb.x, bb.y);
                mma16816(acc[1][tt], (const uint32_t*)&AL[1][c], bb.x, bb.y);
                mma16816(acc[0][tt], (const uint32_t*)&AH[0][c], bb.z, bb.w);
                mma16816(acc[1][tt], (const uint32_t*)&AH[1][c], bb.z, bb.w);
            }
        }

        const int nxt = cur ^ 1;
        #pragma unroll
        for (int m = 0; m < 2; m++) {
            const int r0 = rb2 * 32 + m * 16 + g4;
            #pragma unroll
            for (int jt = 0; jt < 2; jt++) {
                const float* cr  = acc[m][jt];
                const float* cz  = acc[m][2 + jt];
                const float* cnh = acc[m][4 + jt];
                const float* cnx = acc[m][6 + jt];
                float* hr = &hreg[m][jt * 4];
                #pragma unroll
                for (int c = 0; c < 4; c++) {
                    const float r = sigapx(cr[c]);
                    const float z = sigapx(cz[c]);
                    const float n = tanhapx(fmaf(r, cnh[c], cnx[c]));
                    hr[c] = fmaf(z, hr[c] - n, n);
                }
                const int k_abs = 8 + q * 16 + jt * 8 + tk * 2;
                const int c4 = k_abs >> 4, kl = k_abs & 15;
                const int tkc = (kl & 7) >> 1, kb8 = (kl >> 3) & 1;
                uint32_t lo0, hi0 = packsplit(hr[0], hr[1], &lo0);
                uint32_t lo1, hi1 = packsplit(hr[2], hr[3], &lo1);
                uint32_t* d = &s->PA[nxt][(((rb2 * 2 + m) * 8 + g4) * 4 + tkc) * PA_STRIDE
                                          + c4 * 8 + kb8 * 2];
                *(uint2*)d       = make_uint2(hi0, hi1);
                *(uint2*)(d + 4) = make_uint2(lo0, lo1);
                // fp32 h for the output projection
                const int col0 = q * 16 + jt * 8 + tk * 2;
                s->h32[r0 * 65 + col0]           = hr[0];
                s->h32[r0 * 65 + col0 + 1]       = hr[1];
                s->h32[(r0 + 8) * 65 + col0]     = hr[2];
                s->h32[(r0 + 8) * 65 + col0 + 1] = hr[3];
            }
        }
        __syncthreads();             // h32 + PA[nxt] h-words visible

        // output projection: 2 outs per thread over K=64
        float a0 = s->bout_s[2 * o2], a1 = s->bout_s[2 * o2 + 1];
        const float* hrow = &s->h32[prow * 65];
        #pragma unroll 8
        for (int k = 0; k < 64; k++) {
            const float hv = hrow[k];
            a0 = fmaf(hv, s->wout[k * 8 + 2 * o2], a0);
            a1 = fmaf(hv, s->wout[k * 8 + 2 * o2 + 1], a1);
        }
        float* op = out + (((size_t)t) * BATCH + b0 + prow) * 8 + 2 * o2;
        *(float2*)op = make_float2(a0, a1);

        // feedback as next decoder input x: k pair p = o2, row half frh
        {
            const int frt = prow >> 4, fg4 = prow & 7, frh = (prow >> 3) & 1;
            uint32_t* d = &s->PA[nxt][((frt * 8 + fg4) * 4 + o2) * PA_STRIDE];
            uint32_t lo, hi = packsplit(a0, a1, &lo);
            d[frh]     = hi;
            d[4 + frh] = lo;
        }
        __syncthreads();
        cur ^= 1;
    }
}

extern "C" void kernel_launch(void* const* d_in, const int* in_sizes, int n_in,
                              void* d_out, int out_size) {
    const float* x    = (const float*)d_in[0];
    const float* xy   = (const float*)d_in[1];
    const float* eWih = (const float*)d_in[2];
    const float* eWhh = (const float*)d_in[3];
    const float* ebih = (const float*)d_in[4];
    const float* ebhh = (const float*)d_in[5];
    const float* dWih = (const float*)d_in[6];
    const float* dWhh = (const float*)d_in[7];
    const float* dbih = (const float*)d_in[8];
    const float* dbhh = (const float*)d_in[9];
    const float* Wout = (const float*)d_in[10];
    const float* bout = (const float*)d_in[11];
    float* out = (float*)d_out;

    const int smem_bytes = (int)sizeof(SmemR);
    cudaFuncSetAttribute(seq2seq_hmma_kernel,
                         cudaFuncAttributeMaxDynamicSharedMemorySize, smem_bytes);

    seq2seq_hmma_kernel<<<NCTA, NTH, smem_bytes>>>(
        x, xy, eWih, eWhh, ebih, ebhh, dWih, dWhh, dbih, dbhh, Wout, bout, out);
}